// round 14
// baseline (speedup 1.0000x reference)
#include <cuda_runtime.h>
#include <cstdint>

#define FILLV (-1000.0f)
#define NEG_BIG (-3.0e38f)

// Per-batch scratch (allocation-free rule: __device__ globals).
__device__ float g_total[512];
__device__ float g_real[512];

// ---- f32x2 / b64 helpers (validated on sm_103a: add/mul/fma only) --------
__device__ __forceinline__ unsigned long long pk2(float x, float y) {
    unsigned long long r;
    asm("mov.b64 %0, {%1, %2};" : "=l"(r) : "f"(x), "f"(y));
    return r;
}
__device__ __forceinline__ void upk2(unsigned long long a, float& x, float& y) {
    asm("mov.b64 {%0, %1}, %2;" : "=f"(x), "=f"(y) : "l"(a));
}
__device__ __forceinline__ unsigned long long fma2(unsigned long long a,
                                                   unsigned long long b,
                                                   unsigned long long c) {
    unsigned long long r;
    asm("fma.rn.f32x2 %0, %1, %2, %3;" : "=l"(r) : "l"(a), "l"(b), "l"(c));
    return r;
}
__device__ __forceinline__ unsigned long long add2(unsigned long long a,
                                                   unsigned long long b) {
    unsigned long long r;
    asm("add.rn.f32x2 %0, %1, %2;" : "=l"(r) : "l"(a), "l"(b));
    return r;
}

// ---- forward (total path score) kernel -----------------------------------
// 4 batches per CTA, grid = 128, block = 256.
// Thread t: column jj = t & 127, row-half h = t >> 7 (rows h*64 .. h*64+63).
// Register tables: Tc2[32] + Ep[32] (shared across all 4 batches).
// spcw transposed ([g][2*jj+h]) -> phaseC reads ONE LDS.128 per batch.
// swS/swM as float4 -> phaseC reads ONE LDS.128 per array per batch.
// Fully deferred scalar work (R11/R12 scheme): contrib exp + shfl reduction
// for step s-1 run at the top of step s, interleaved with phase 0.
__global__ void __launch_bounds__(256, 1)
crf_forward_kernel(const float* __restrict__ em, const float* __restrict__ trans) {
    __shared__ ulonglong2 shpv[4][64];    // per batch: {p[2m],p[2m+1] | v[2m],v[2m+1]}
    __shared__ float2 spcw[4][256];       // per batch: (cm, w) at [g][2*jj + h]
    __shared__ float scol[128];           // colmax of transitions
    __shared__ float4 swS[4];             // warp partials: sum(contrib), one float per warp
    __shared__ float4 swM[4];             // warp partials: max(pnew)

    const int t  = threadIdx.x;
    const int jj = t & 127;
    const int h  = t >> 7;
    const int wi = (t >> 5) & 3;
    const int b0 = blockIdx.x * 4;
    const int rowbase = h * 64;
    const int g0 = 2 * h, g1 = g0 + 1;

    // --- load T column slice, colmax, packed Tc2 / Ep tables (registers) ---
    float Tcs[64];
    float tcm = NEG_BIG;
#pragma unroll
    for (int k = 0; k < 64; ++k) {
        float tv = trans[(rowbase + k) * 128 + jj];
        Tcs[k] = tv;
        tcm = fmaxf(tcm, tv);
    }
    ((float*)spcw)[t] = tcm;
    __syncthreads();
    if (t < 128) scol[t] = fmaxf(((float*)spcw)[t], ((float*)spcw)[t + 128]);
    __syncthreads();
    const float colmax = scol[jj];

    unsigned long long Tc2[32], Ep[32];
#pragma unroll
    for (int k = 0; k < 32; ++k) {
        Tc2[k] = pk2(Tcs[2 * k], Tcs[2 * k + 1]);
        Ep[k]  = pk2(expf(Tcs[2 * k] - colmax), expf(Tcs[2 * k + 1] - colmax));
    }

    // --- init state for owned batches (normalizer P = 0) ---
    {
        float p  = (jj == 126) ? 0.0f : FILLV;
        float vv = (jj == 126) ? 1.0f : 0.0f;
        int m = jj >> 1, lane = jj & 1;
        float* pvf0 = (float*)(shpv[g0]);
        float* pvf1 = (float*)(shpv[g1]);
        pvf0[m * 4 + lane] = p;  pvf0[m * 4 + 2 + lane] = vv;
        pvf1[m * 4 + lane] = p;  pvf1[m * 4 + 2 + lane] = vv;
    }
    float P0 = 0.0f, P1 = 0.0f;         // normalizer of currently-published v
    float PdP0 = 0.0f, PdP1 = 0.0f;     // normalizer of w at prev step (lag-2)
    float cP0 = 0.0f, cP1 = 0.0f;       // prev step c (deferred contrib input)
    float wP0 = 0.0f, wP1 = 0.0f;       // prev step w
    float pnP0 = 0.0f, pnP1 = 0.0f;     // prev step pnew (deferred max input)
    float Lacc0 = 0.0f, Lacc1 = 0.0f;
    float vkeep0 = 0.0f, vkeep1 = 0.0f;
    __syncthreads();

    const float* embp0 = em + (size_t)(b0 + g0) * 512 * 126;
    const float* embp1 = embp0 + 512 * 126;

    float obs_c0 = (jj < 126) ? embp0[jj] : FILLV;
    float obs_c1 = (jj < 126) ? embp1[jj] : FILLV;

    const ulonglong2* const pvA = shpv[0] + h * 32;
    const ulonglong2* const pvB = shpv[1] + h * 32;
    const ulonglong2* const pvC = shpv[2] + h * 32;
    const ulonglong2* const pvD = shpv[3] + h * 32;

    for (int s = 1; s <= 513; ++s) {
        // --- deferred section for step s-1 (interleaves with phase 0) ---
        if (s > 1) {
            float contrib0 = __expf(PdP0 + colmax - cP0) * wP0;
            float contrib1 = __expf(PdP1 + colmax - cP1) * wP1;
            float sr0 = contrib0, mr0 = pnP0;
            float sr1 = contrib1, mr1 = pnP1;
#pragma unroll
            for (int o = 16; o; o >>= 1) {
                float a0 = __shfl_xor_sync(0xffffffffu, sr0, o);
                float m0 = __shfl_xor_sync(0xffffffffu, mr0, o);
                float a1 = __shfl_xor_sync(0xffffffffu, sr1, o);
                float m1 = __shfl_xor_sync(0xffffffffu, mr1, o);
                sr0 += a0; mr0 = fmaxf(mr0, m0);
                sr1 += a1; mr1 = fmaxf(mr1, m1);
            }
            if ((t & 31) == 0) {
                ((float*)&swS[g0])[wi] = sr0; ((float*)&swM[g0])[wi] = mr0;
                ((float*)&swS[g1])[wi] = sr1; ((float*)&swM[g1])[wi] = mr1;
            }
        }

        // Prefetch next step's observations (hidden behind phase 0).
        float obs_n0, obs_n1;
        if (s + 1 <= 512) {
            obs_n0 = (jj < 126) ? embp0[(size_t)s * 126 + jj] : FILLV;
            obs_n1 = (jj < 126) ? embp1[(size_t)s * 126 + jj] : FILLV;
        } else {
            float v = (jj == 127) ? 0.0f : FILLV;  // END pseudo-row
            obs_n0 = v; obs_n1 = v;
        }

        // --- phase 0: max-plus + matvec over 64 rows x 4 batches ---
        float cm0A = NEG_BIG, cm1A = NEG_BIG;
        float cm0B = NEG_BIG, cm1B = NEG_BIG;
        float cm0C = NEG_BIG, cm1C = NEG_BIG;
        float cm0D = NEG_BIG, cm1D = NEG_BIG;
        unsigned long long wA = 0ULL, wB = 0ULL, wC = 0ULL, wD = 0ULL;
#pragma unroll
        for (int k = 0; k < 32; ++k) {
            ulonglong2 qA = pvA[k];
            ulonglong2 qB = pvB[k];
            ulonglong2 qC = pvC[k];
            ulonglong2 qD = pvD[k];
            float s0, s1;
            unsigned long long u;
            u = add2(qA.x, Tc2[k]); upk2(u, s0, s1);
            cm0A = fmaxf(cm0A, s0); cm1A = fmaxf(cm1A, s1);
            wA = fma2(qA.y, Ep[k], wA);
            u = add2(qB.x, Tc2[k]); upk2(u, s0, s1);
            cm0B = fmaxf(cm0B, s0); cm1B = fmaxf(cm1B, s1);
            wB = fma2(qB.y, Ep[k], wB);
            u = add2(qC.x, Tc2[k]); upk2(u, s0, s1);
            cm0C = fmaxf(cm0C, s0); cm1C = fmaxf(cm1C, s1);
            wC = fma2(qC.y, Ep[k], wC);
            u = add2(qD.x, Tc2[k]); upk2(u, s0, s1);
            cm0D = fmaxf(cm0D, s0); cm1D = fmaxf(cm1D, s1);
            wD = fma2(qD.y, Ep[k], wD);
        }
        {
            float w0, w1;
            upk2(wA, w0, w1); spcw[0][2 * jj + h] = make_float2(fmaxf(cm0A, cm1A), w0 + w1);
            upk2(wB, w0, w1); spcw[1][2 * jj + h] = make_float2(fmaxf(cm0B, cm1B), w0 + w1);
            upk2(wC, w0, w1); spcw[2][2 * jj + h] = make_float2(fmaxf(cm0C, cm1C), w0 + w1);
            upk2(wD, w0, w1); spcw[3][2 * jj + h] = make_float2(fmaxf(cm0D, cm1D), w0 + w1);
        }
        __syncthreads();

        // --- phaseC: minimal critical path for owned batches ---
        float4 z0 = *reinterpret_cast<const float4*>(&spcw[g0][2 * jj]);
        float4 z1 = *reinterpret_cast<const float4*>(&spcw[g1][2 * jj]);
        float c0 = fmaxf(z0.x, z0.z), w0 = z0.y + z0.w;
        float c1 = fmaxf(z1.x, z1.z), w1 = z1.y + z1.w;
        float pnew0 = obs_c0 + c0;
        float pnew1 = obs_c1 + c1;

        float M0, M1;
        if (s > 1) {
            float4 m0v = swM[g0];
            float4 m1v = swM[g1];
            M0 = fmaxf(fmaxf(m0v.x, m0v.y), fmaxf(m0v.z, m0v.w));
            M1 = fmaxf(fmaxf(m1v.x, m1v.y), fmaxf(m1v.z, m1v.w));
        } else {
            M0 = 0.0f; M1 = 0.0f;
        }

        float v0 = __expf(pnew0 - M0);
        float v1 = __expf(pnew1 - M1);
        vkeep0 = v0; vkeep1 = v1;
        {
            int m = jj >> 1, lane = jj & 1;
            float* pvf0 = (float*)(shpv[g0]);
            float* pvf1 = (float*)(shpv[g1]);
            pvf0[m * 4 + lane] = pnew0;  pvf0[m * 4 + 2 + lane] = v0;
            pvf1[m * 4 + lane] = pnew1;  pvf1[m * 4 + 2 + lane] = v1;
        }

        // Off-path accumulation: Lacc += log(S_{s-1})
        if (s > 1) {
            float4 s0v = swS[g0];
            float4 s1v = swS[g1];
            Lacc0 += __logf((s0v.x + s0v.y) + (s0v.z + s0v.w));
            Lacc1 += __logf((s1v.x + s1v.y) + (s1v.z + s1v.w));
        }

        // Roll deferred state.
        PdP0 = P0; PdP1 = P1;
        P0 = M0;  P1 = M1;
        cP0 = c0; cP1 = c1;
        wP0 = w0; wP1 = w1;
        pnP0 = pnew0; pnP1 = pnew1;

        __syncthreads();
        obs_c0 = obs_n0;
        obs_c1 = obs_n1;
    }

    // --- epilogue: flush step-513 deferred contrib + final log-sum-exp ---
    {
        float contrib0 = __expf(PdP0 + colmax - cP0) * wP0;
        float contrib1 = __expf(PdP1 + colmax - cP1) * wP1;
        float sr0 = contrib0, sv0 = vkeep0;
        float sr1 = contrib1, sv1 = vkeep1;
#pragma unroll
        for (int o = 16; o; o >>= 1) {
            sr0 += __shfl_xor_sync(0xffffffffu, sr0, o);
            sv0 += __shfl_xor_sync(0xffffffffu, sv0, o);
            sr1 += __shfl_xor_sync(0xffffffffu, sr1, o);
            sv1 += __shfl_xor_sync(0xffffffffu, sv1, o);
        }
        if ((t & 31) == 0) {
            ((float*)&swS[g0])[wi] = sr0; ((float*)&swM[g0])[wi] = sv0;  // swM reused as sum(v)
            ((float*)&swS[g1])[wi] = sr1; ((float*)&swM[g1])[wi] = sv1;
        }
    }
    __syncthreads();
    if (jj == 0) {
        float4 sS0 = swS[g0], sS1 = swS[g1];
        float4 sV0 = swM[g0], sV1 = swM[g1];
        float S0 = (sS0.x + sS0.y) + (sS0.z + sS0.w);
        float S1 = (sS1.x + sS1.y) + (sS1.z + sS1.w);
        float Sv0 = (sV0.x + sV0.y) + (sV0.z + sV0.w);
        float Sv1 = (sV1.x + sV1.y) + (sV1.z + sV1.w);
        g_total[b0 + g0] = P0 + logf(Sv0) + Lacc0 + logf(S0);
        g_total[b0 + g1] = P1 + logf(Sv1) + Lacc1 + logf(S1);
    }
}

// ---- gold-path score kernel ----------------------------------------------
__global__ void crf_real_kernel(const float* __restrict__ em,
                                const int* __restrict__ labels,
                                const float* __restrict__ trans) {
    const int b = blockIdx.x;
    const int t = threadIdx.x;   // 128 threads
    __shared__ float sw[4];
    const int* lb = labels + b * 512;
    const float* emb = em + (size_t)b * 512 * 126;

    float acc = 0.0f;
    for (int tt = t; tt < 512; tt += 128) {
        int l0 = lb[tt];
        acc += emb[tt * 126 + l0];
        int l1 = (tt < 511) ? lb[tt + 1] : 127;     // END = L+1 = 127
        acc += trans[l0 * 128 + l1];
    }
    if (t == 0) acc += trans[126 * 128 + lb[0]];     // START = L = 126

#pragma unroll
    for (int o = 16; o; o >>= 1) acc += __shfl_xor_sync(0xffffffffu, acc, o);
    if ((t & 31) == 0) sw[t >> 5] = acc;
    __syncthreads();
    if (t == 0) g_real[b] = (sw[0] + sw[1]) + (sw[2] + sw[3]);
}

// ---- fixed-order final reduction (deterministic) -------------------------
__global__ void crf_reduce_kernel(float* __restrict__ out) {
    const int t = threadIdx.x;   // 512 threads
    __shared__ float sw[16];
    float d = g_total[t] - g_real[t];
#pragma unroll
    for (int o = 16; o; o >>= 1) d += __shfl_xor_sync(0xffffffffu, d, o);
    if ((t & 31) == 0) sw[t >> 5] = d;
    __syncthreads();
    if (t == 0) {
        float s = 0.0f;
#pragma unroll
        for (int w = 0; w < 16; ++w) s += sw[w];
        out[0] = s;
    }
}

extern "C" void kernel_launch(void* const* d_in, const int* in_sizes, int n_in,
                              void* d_out, int out_size) {
    const float* em     = (const float*)d_in[0];   // [512, 512, 126] f32
    const int*   labels = (const int*)d_in[1];     // [512, 512] i32
    const float* trans  = (const float*)d_in[2];   // [128, 128] f32

    crf_forward_kernel<<<128, 256>>>(em, trans);
    crf_real_kernel<<<512, 128>>>(em, labels, trans);
    crf_reduce_kernel<<<1, 512>>>((float*)d_out);
}

// round 15
// speedup vs baseline: 1.6582x; 1.6582x over previous
#include <cuda_runtime.h>
#include <cstdint>

#define FILLV (-1000.0f)
#define NEG_BIG (-3.0e38f)

// Per-batch scratch (allocation-free rule: __device__ globals).
__device__ float g_total[512];
__device__ float g_real[512];

// ---- f32x2 / b64 helpers (validated on sm_103a: add/mul/fma only) --------
__device__ __forceinline__ unsigned long long pk2(float x, float y) {
    unsigned long long r;
    asm("mov.b64 %0, {%1, %2};" : "=l"(r) : "f"(x), "f"(y));
    return r;
}
__device__ __forceinline__ void upk2(unsigned long long a, float& x, float& y) {
    asm("mov.b64 {%0, %1}, %2;" : "=f"(x), "=f"(y) : "l"(a));
}
__device__ __forceinline__ unsigned long long fma2(unsigned long long a,
                                                   unsigned long long b,
                                                   unsigned long long c) {
    unsigned long long r;
    asm("fma.rn.f32x2 %0, %1, %2, %3;" : "=l"(r) : "l"(a), "l"(b), "l"(c));
    return r;
}
__device__ __forceinline__ unsigned long long add2(unsigned long long a,
                                                   unsigned long long b) {
    unsigned long long r;
    asm("add.rn.f32x2 %0, %1, %2;" : "=l"(r) : "l"(a), "l"(b));
    return r;
}

// ---- forward (total path score) kernel -----------------------------------
// 4 batches per CTA, grid = 128, block = 256  (R12 structure, 770 us proven).
// Thread t: column jj = t & 127, row-half h = t >> 7 (rows h*64 .. h*64+63).
// Register tables: Tc2[32] + Ep[32] (shared across all 4 batches).
// spc/spw: separate float arrays, conflict-free 4B-stride STS/LDS (R12 layout).
// Fully deferred scalar work: contrib exp + shfl reduction for step s-1 run
// at the top of step s, interleaved with phase 0.
// Only delta vs R12: swS/swM combined reads via one LDS.128 each (aligned,
// store addresses identical).
__global__ void __launch_bounds__(256, 1)
crf_forward_kernel(const float* __restrict__ em, const float* __restrict__ trans) {
    __shared__ ulonglong2 shpv[4][64];    // per batch: {p[2m],p[2m+1] | v[2m],v[2m+1]}
    __shared__ float spc[4][256];         // per batch: per-thread partial column max
    __shared__ float spw[4][256];         // per batch: per-thread partial matvec sum
    __shared__ float scol[128];           // colmax of transitions
    __shared__ __align__(16) float swS[4][4];   // warp partials: sum(contrib)
    __shared__ __align__(16) float swM[4][4];   // warp partials: max(pnew)

    const int t  = threadIdx.x;
    const int jj = t & 127;
    const int h  = t >> 7;
    const int wi = (t >> 5) & 3;
    const int b0 = blockIdx.x * 4;
    const int rowbase = h * 64;
    const int g0 = 2 * h, g1 = g0 + 1;

    // --- load T column slice, colmax, packed Tc2 / Ep tables (registers) ---
    float Tcs[64];
    float tcm = NEG_BIG;
#pragma unroll
    for (int k = 0; k < 64; ++k) {
        float tv = trans[(rowbase + k) * 128 + jj];
        Tcs[k] = tv;
        tcm = fmaxf(tcm, tv);
    }
    spc[0][t] = tcm;
    __syncthreads();
    if (t < 128) scol[t] = fmaxf(spc[0][t], spc[0][t + 128]);
    __syncthreads();
    const float colmax = scol[jj];

    unsigned long long Tc2[32], Ep[32];
#pragma unroll
    for (int k = 0; k < 32; ++k) {
        Tc2[k] = pk2(Tcs[2 * k], Tcs[2 * k + 1]);
        Ep[k]  = pk2(expf(Tcs[2 * k] - colmax), expf(Tcs[2 * k + 1] - colmax));
    }

    // --- init state for owned batches (normalizer P = 0) ---
    {
        float p  = (jj == 126) ? 0.0f : FILLV;
        float vv = (jj == 126) ? 1.0f : 0.0f;
        int m = jj >> 1, lane = jj & 1;
        float* pvf0 = (float*)(shpv[g0]);
        float* pvf1 = (float*)(shpv[g1]);
        pvf0[m * 4 + lane] = p;  pvf0[m * 4 + 2 + lane] = vv;
        pvf1[m * 4 + lane] = p;  pvf1[m * 4 + 2 + lane] = vv;
    }
    float P0 = 0.0f, P1 = 0.0f;         // normalizer of currently-published v
    float PdP0 = 0.0f, PdP1 = 0.0f;     // normalizer of w at prev step (lag-2)
    float cP0 = 0.0f, cP1 = 0.0f;       // prev step c (deferred contrib input)
    float wP0 = 0.0f, wP1 = 0.0f;       // prev step w
    float pnP0 = 0.0f, pnP1 = 0.0f;     // prev step pnew (deferred max input)
    float Lacc0 = 0.0f, Lacc1 = 0.0f;
    float vkeep0 = 0.0f, vkeep1 = 0.0f;
    __syncthreads();

    const float* embp0 = em + (size_t)(b0 + g0) * 512 * 126;
    const float* embp1 = embp0 + 512 * 126;

    float obs_c0 = (jj < 126) ? embp0[jj] : FILLV;
    float obs_c1 = (jj < 126) ? embp1[jj] : FILLV;

    const ulonglong2* const pvA = shpv[0] + h * 32;
    const ulonglong2* const pvB = shpv[1] + h * 32;
    const ulonglong2* const pvC = shpv[2] + h * 32;
    const ulonglong2* const pvD = shpv[3] + h * 32;

    for (int s = 1; s <= 513; ++s) {
        // --- deferred section for step s-1 (interleaves with phase 0) ---
        if (s > 1) {
            float contrib0 = __expf(PdP0 + colmax - cP0) * wP0;
            float contrib1 = __expf(PdP1 + colmax - cP1) * wP1;
            float sr0 = contrib0, mr0 = pnP0;
            float sr1 = contrib1, mr1 = pnP1;
#pragma unroll
            for (int o = 16; o; o >>= 1) {
                float a0 = __shfl_xor_sync(0xffffffffu, sr0, o);
                float m0 = __shfl_xor_sync(0xffffffffu, mr0, o);
                float a1 = __shfl_xor_sync(0xffffffffu, sr1, o);
                float m1 = __shfl_xor_sync(0xffffffffu, mr1, o);
                sr0 += a0; mr0 = fmaxf(mr0, m0);
                sr1 += a1; mr1 = fmaxf(mr1, m1);
            }
            if ((t & 31) == 0) {
                swS[g0][wi] = sr0; swM[g0][wi] = mr0;
                swS[g1][wi] = sr1; swM[g1][wi] = mr1;
            }
        }

        // Prefetch next step's observations (hidden behind phase 0).
        float obs_n0, obs_n1;
        if (s + 1 <= 512) {
            obs_n0 = (jj < 126) ? embp0[(size_t)s * 126 + jj] : FILLV;
            obs_n1 = (jj < 126) ? embp1[(size_t)s * 126 + jj] : FILLV;
        } else {
            float v = (jj == 127) ? 0.0f : FILLV;  // END pseudo-row
            obs_n0 = v; obs_n1 = v;
        }

        // --- phase 0: max-plus + matvec over 64 rows x 4 batches ---
        float cm0A = NEG_BIG, cm1A = NEG_BIG;
        float cm0B = NEG_BIG, cm1B = NEG_BIG;
        float cm0C = NEG_BIG, cm1C = NEG_BIG;
        float cm0D = NEG_BIG, cm1D = NEG_BIG;
        unsigned long long wA = 0ULL, wB = 0ULL, wC = 0ULL, wD = 0ULL;
#pragma unroll
        for (int k = 0; k < 32; ++k) {
            ulonglong2 qA = pvA[k];
            ulonglong2 qB = pvB[k];
            ulonglong2 qC = pvC[k];
            ulonglong2 qD = pvD[k];
            float s0, s1;
            unsigned long long u;
            u = add2(qA.x, Tc2[k]); upk2(u, s0, s1);
            cm0A = fmaxf(cm0A, s0); cm1A = fmaxf(cm1A, s1);
            wA = fma2(qA.y, Ep[k], wA);
            u = add2(qB.x, Tc2[k]); upk2(u, s0, s1);
            cm0B = fmaxf(cm0B, s0); cm1B = fmaxf(cm1B, s1);
            wB = fma2(qB.y, Ep[k], wB);
            u = add2(qC.x, Tc2[k]); upk2(u, s0, s1);
            cm0C = fmaxf(cm0C, s0); cm1C = fmaxf(cm1C, s1);
            wC = fma2(qC.y, Ep[k], wC);
            u = add2(qD.x, Tc2[k]); upk2(u, s0, s1);
            cm0D = fmaxf(cm0D, s0); cm1D = fmaxf(cm1D, s1);
            wD = fma2(qD.y, Ep[k], wD);
        }
        {
            float w0, w1;
            upk2(wA, w0, w1); spc[0][t] = fmaxf(cm0A, cm1A); spw[0][t] = w0 + w1;
            upk2(wB, w0, w1); spc[1][t] = fmaxf(cm0B, cm1B); spw[1][t] = w0 + w1;
            upk2(wC, w0, w1); spc[2][t] = fmaxf(cm0C, cm1C); spw[2][t] = w0 + w1;
            upk2(wD, w0, w1); spc[3][t] = fmaxf(cm0D, cm1D); spw[3][t] = w0 + w1;
        }
        __syncthreads();

        // --- phaseC: minimal critical path for owned batches ---
        float c0 = fmaxf(spc[g0][jj], spc[g0][128 + jj]);
        float w0 = spw[g0][jj] + spw[g0][128 + jj];
        float c1 = fmaxf(spc[g1][jj], spc[g1][128 + jj]);
        float w1 = spw[g1][jj] + spw[g1][128 + jj];
        float pnew0 = obs_c0 + c0;
        float pnew1 = obs_c1 + c1;

        float M0, M1;
        if (s > 1) {
            float4 m0v = *reinterpret_cast<const float4*>(&swM[g0][0]);
            float4 m1v = *reinterpret_cast<const float4*>(&swM[g1][0]);
            M0 = fmaxf(fmaxf(m0v.x, m0v.y), fmaxf(m0v.z, m0v.w));
            M1 = fmaxf(fmaxf(m1v.x, m1v.y), fmaxf(m1v.z, m1v.w));
        } else {
            M0 = 0.0f; M1 = 0.0f;
        }

        float v0 = __expf(pnew0 - M0);
        float v1 = __expf(pnew1 - M1);
        vkeep0 = v0; vkeep1 = v1;
        {
            int m = jj >> 1, lane = jj & 1;
            float* pvf0 = (float*)(shpv[g0]);
            float* pvf1 = (float*)(shpv[g1]);
            pvf0[m * 4 + lane] = pnew0;  pvf0[m * 4 + 2 + lane] = v0;
            pvf1[m * 4 + lane] = pnew1;  pvf1[m * 4 + 2 + lane] = v1;
        }

        // Off-path accumulation: Lacc += log(S_{s-1})
        if (s > 1) {
            float4 s0v = *reinterpret_cast<const float4*>(&swS[g0][0]);
            float4 s1v = *reinterpret_cast<const float4*>(&swS[g1][0]);
            Lacc0 += __logf((s0v.x + s0v.y) + (s0v.z + s0v.w));
            Lacc1 += __logf((s1v.x + s1v.y) + (s1v.z + s1v.w));
        }

        // Roll deferred state.
        PdP0 = P0; PdP1 = P1;
        P0 = M0;  P1 = M1;
        cP0 = c0; cP1 = c1;
        wP0 = w0; wP1 = w1;
        pnP0 = pnew0; pnP1 = pnew1;

        __syncthreads();
        obs_c0 = obs_n0;
        obs_c1 = obs_n1;
    }

    // --- epilogue: flush step-513 deferred contrib + final log-sum-exp ---
    {
        float contrib0 = __expf(PdP0 + colmax - cP0) * wP0;
        float contrib1 = __expf(PdP1 + colmax - cP1) * wP1;
        float sr0 = contrib0, sv0 = vkeep0;
        float sr1 = contrib1, sv1 = vkeep1;
#pragma unroll
        for (int o = 16; o; o >>= 1) {
            sr0 += __shfl_xor_sync(0xffffffffu, sr0, o);
            sv0 += __shfl_xor_sync(0xffffffffu, sv0, o);
            sr1 += __shfl_xor_sync(0xffffffffu, sr1, o);
            sv1 += __shfl_xor_sync(0xffffffffu, sv1, o);
        }
        if ((t & 31) == 0) {
            swS[g0][wi] = sr0; swM[g0][wi] = sv0;   // swM reused as sum(v)
            swS[g1][wi] = sr1; swM[g1][wi] = sv1;
        }
    }
    __syncthreads();
    if (jj == 0) {
        float S0 = (swS[g0][0] + swS[g0][1]) + (swS[g0][2] + swS[g0][3]);
        float S1 = (swS[g1][0] + swS[g1][1]) + (swS[g1][2] + swS[g1][3]);
        float Sv0 = (swM[g0][0] + swM[g0][1]) + (swM[g0][2] + swM[g0][3]);
        float Sv1 = (swM[g1][0] + swM[g1][1]) + (swM[g1][2] + swM[g1][3]);
        g_total[b0 + g0] = P0 + logf(Sv0) + Lacc0 + logf(S0);
        g_total[b0 + g1] = P1 + logf(Sv1) + Lacc1 + logf(S1);
    }
}

// ---- gold-path score kernel ----------------------------------------------
__global__ void crf_real_kernel(const float* __restrict__ em,
                                const int* __restrict__ labels,
                                const float* __restrict__ trans) {
    const int b = blockIdx.x;
    const int t = threadIdx.x;   // 128 threads
    __shared__ float sw[4];
    const int* lb = labels + b * 512;
    const float* emb = em + (size_t)b * 512 * 126;

    float acc = 0.0f;
    for (int tt = t; tt < 512; tt += 128) {
        int l0 = lb[tt];
        acc += emb[tt * 126 + l0];
        int l1 = (tt < 511) ? lb[tt + 1] : 127;     // END = L+1 = 127
        acc += trans[l0 * 128 + l1];
    }
    if (t == 0) acc += trans[126 * 128 + lb[0]];     // START = L = 126

#pragma unroll
    for (int o = 16; o; o >>= 1) acc += __shfl_xor_sync(0xffffffffu, acc, o);
    if ((t & 31) == 0) sw[t >> 5] = acc;
    __syncthreads();
    if (t == 0) g_real[b] = (sw[0] + sw[1]) + (sw[2] + sw[3]);
}

// ---- fixed-order final reduction (deterministic) -------------------------
__global__ void crf_reduce_kernel(float* __restrict__ out) {
    const int t = threadIdx.x;   // 512 threads
    __shared__ float sw[16];
    float d = g_total[t] - g_real[t];
#pragma unroll
    for (int o = 16; o; o >>= 1) d += __shfl_xor_sync(0xffffffffu, d, o);
    if ((t & 31) == 0) sw[t >> 5] = d;
    __syncthreads();
    if (t == 0) {
        float s = 0.0f;
#pragma unroll
        for (int w = 0; w < 16; ++w) s += sw[w];
        out[0] = s;
    }
}

extern "C" void kernel_launch(void* const* d_in, const int* in_sizes, int n_in,
                              void* d_out, int out_size) {
    const float* em     = (const float*)d_in[0];   // [512, 512, 126] f32
    const int*   labels = (const int*)d_in[1];     // [512, 512] i32
    const float* trans  = (const float*)d_in[2];   // [128, 128] f32

    crf_forward_kernel<<<128, 256>>>(em, trans);
    crf_real_kernel<<<512, 128>>>(em, labels, trans);
    crf_reduce_kernel<<<1, 512>>>((float*)d_out);
}